// round 16
// baseline (speedup 1.0000x reference)
#include <cuda_runtime.h>
#include <cuda_bf16.h>

#define N 8192
#define F 64
#define TILES 32           // sorted key tiles of 256
#define TSZ 256
#define CHN 2048           // scan chunks
#define CSZ 4              // ranks per chunk
#define NBLK 256
#define NTHR 512

typedef unsigned long long u64;

// ---------------- scratch (no allocations allowed) ----------------
__device__ float g_ltg[N * F];
__device__ float g_ssrc[N];
__device__ float g_sdst[N];
__device__ float g_P[N];
__device__ float g_p[N];
__device__ float g_Qs[N];
__device__ float g_qs[N];
__device__ u64   g_key[N];            // (sortable(sdst)<<32)|idx — unique
__device__ u64   g_tkey[TILES][TSZ];  // per-tile sorted keys (flat-contiguous)
__device__ int   g_perm[N];
__device__ float g_qP[N];             // qs permuted by rank
__device__ float g_QP[N];             // Qs permuted by rank
__device__ float g_sorted[N + 32];    // sdst ascending; +32 pad of +inf
__device__ float g_ctqT[65][CHN];     // transposed chunk totals; row 64 = scalar
__device__ float g_ctQT[65][CHN];
__device__ float g_coq[CHN + 1][72];  // exclusive chunk offsets; row CHN = totals
__device__ float g_coQ[CHN + 1][72];
__device__ unsigned int g_barc[8];    // monotonic barrier counters (replay-safe)

__device__ __forceinline__ unsigned int f2sort(float f) {
    unsigned int u = __float_as_uint(f);
    return (u & 0x80000000u) ? ~u : (u | 0x80000000u);
}

// Simple grid barrier (measured best): monotonic counter + generation
// arithmetic; volatile poll. 256 blocks, launch_bounds(512,2) -> co-resident.
__device__ __forceinline__ void gbar(int id) {
    __syncthreads();
    if (threadIdx.x == 0) {
        __threadfence();
        unsigned int old = atomicAdd(&g_barc[id], 1u);
        unsigned int target = (old / NBLK + 1u) * NBLK;
        volatile unsigned int* p = &g_barc[id];
        while (*p < target) { __nanosleep(64); }
        __threadfence();
    }
    __syncthreads();
}

__global__ __launch_bounds__(NTHR, 2)
void gat_fused(const float* __restrict__ graph,
               const float* __restrict__ W,
               const float* __restrict__ a,
               float* __restrict__ out) {
    // 32KB shared reuse:
    //  P0/P1: sW [0,16K) + sort tile [16K,18K)
    //  P2:    rank stage, full 32KB
    //  P3b/P5: splitters [0,1K) + partials [1K,25.1K) + chunk ids [25.1K,25.4K)
    __shared__ __align__(16) unsigned char s_buf[32768];
    __shared__ float sa[2 * F];
    __shared__ float swv[2 * F];       // wv1 | wv2
    __shared__ int   sRank[32];
    __shared__ float ssx[16], ssy[16];

    int t = threadIdx.x;
    int blk = blockIdx.x;
    int lane = t & 31;

    float* sW = reinterpret_cast<float*>(s_buf);

    // ============ Phase 0: W->smem, wv = W·a halves, scalars/exps/keys =======
    {
        for (int i = t; i < F * F; i += NTHR) sW[i] = W[i];
        if (t < 2 * F) sa[t] = a[t];
        if (blk == 0 && t < 32) g_sorted[N + t] = __int_as_float(0x7f800000);
        __syncthreads();

        if (t < F) {
            float s1 = 0.f, s2 = 0.f;
            const float4* wr = reinterpret_cast<const float4*>(&sW[t * F]);
            const float4* a1 = reinterpret_cast<const float4*>(&sa[0]);
            const float4* a2 = reinterpret_cast<const float4*>(&sa[F]);
#pragma unroll
            for (int f4 = 0; f4 < F / 4; f4++) {
                float4 w = wr[f4], v1 = a1[f4], v2 = a2[f4];
                s1 += w.x * v1.x + w.y * v1.y + w.z * v1.z + w.w * v1.w;
                s2 += w.x * v2.x + w.y * v2.y + w.z * v2.z + w.w * v2.w;
            }
            swv[t] = s1;
            swv[F + t] = s2;
        }
        __syncthreads();

        int row = blk * 32 + (t >> 4);
        int q = t & 15;
        float4 g = __ldg(&reinterpret_cast<const float4*>(graph)[(size_t)row * 16 + q]);
        float4 w1 = reinterpret_cast<const float4*>(swv)[q];
        float4 w2 = reinterpret_cast<const float4*>(swv)[16 + q];
        float s1 = g.x * w1.x + g.y * w1.y + g.z * w1.z + g.w * w1.w;
        float s2 = g.x * w2.x + g.y * w2.y + g.z * w2.z + g.w * w2.w;
        s1 += __shfl_xor_sync(0xffffffffu, s1, 1);
        s1 += __shfl_xor_sync(0xffffffffu, s1, 2);
        s1 += __shfl_xor_sync(0xffffffffu, s1, 4);
        s1 += __shfl_xor_sync(0xffffffffu, s1, 8);
        s2 += __shfl_xor_sync(0xffffffffu, s2, 1);
        s2 += __shfl_xor_sync(0xffffffffu, s2, 2);
        s2 += __shfl_xor_sync(0xffffffffu, s2, 4);
        s2 += __shfl_xor_sync(0xffffffffu, s2, 8);
        if (q == 0) {
            g_ssrc[row] = s1;
            g_sdst[row] = s2;
            g_P[row]  = expf(s1);
            g_p[row]  = expf(0.2f * s1);
            g_Qs[row] = expf(s2);
            g_qs[row] = expf(0.2f * s2);
            g_key[row] = ((u64)f2sort(s2) << 32) | (unsigned int)row;
        }
    }
    gbar(0);

    // ============ Phase 1: [blk<32: count-sort one tile]  ||  GEMM (all) =====
    {
        u64* sk = reinterpret_cast<u64*>(s_buf + 16384);  // 2KB, above sW
        if (blk < TILES && t < 256) sk[t] = g_key[blk * 256 + t];
        __syncthreads();
        if (blk < TILES && t < 256) {
            u64 mykey = sk[t];
            int cnt = 0;
#pragma unroll 8
            for (int i = 0; i < 256; i++) cnt += (int)(sk[i] < mykey);
            g_tkey[blk][cnt] = mykey;
        }

        // GEMM: 2 rows x 2 features per thread
        int rp = t >> 5;
        int fs2 = (t & 31) * 2;
        int r0 = blk * 32 + rp * 2;
        int r1 = r0 + 1;

        float a00 = 0.f, a01 = 0.f, a10 = 0.f, a11 = 0.f;
        const float4* g4 = reinterpret_cast<const float4*>(graph);
#pragma unroll
        for (int k4i = 0; k4i < F / 4; k4i++) {
            float4 g0 = __ldg(&g4[(size_t)r0 * 16 + k4i]);
            float4 g1 = __ldg(&g4[(size_t)r1 * 16 + k4i]);
            float gv0[4] = {g0.x, g0.y, g0.z, g0.w};
            float gv1[4] = {g1.x, g1.y, g1.z, g1.w};
#pragma unroll
            for (int kk = 0; kk < 4; kk++) {
                float2 w = *reinterpret_cast<const float2*>(&sW[(k4i * 4 + kk) * F + fs2]);
                a00 += gv0[kk] * w.x;
                a01 += gv0[kk] * w.y;
                a10 += gv1[kk] * w.x;
                a11 += gv1[kk] * w.y;
            }
        }
        *reinterpret_cast<float2*>(&g_ltg[(size_t)r0 * F + fs2]) = make_float2(a00, a01);
        *reinterpret_cast<float2*>(&g_ltg[(size_t)r1 * F + fs2]) = make_float2(a10, a11);
    }
    gbar(1);

    // ============ Phase 2: rank — 32 keys x 32 tiles; scatter perm + permuted =
    {
        u64* tb = reinterpret_cast<u64*>(s_buf);  // 4096 u64 = 32KB
        const u64* tkf = &g_tkey[0][0];
        int ki = t & 31;
        int tloc = t >> 5;
        u64 mykey = g_key[blk * 32 + ki];
        if (t < 32) sRank[t] = 0;

#pragma unroll 1
        for (int round = 0; round < 2; round++) {
            __syncthreads();
#pragma unroll
            for (int r = 0; r < 8; r++)
                tb[r * 512 + t] = tkf[round * 4096 + r * 512 + t];
            __syncthreads();

            const u64* tile = tb + tloc * 256;
            int lo = 0, hi = 256;
#pragma unroll
            for (int st = 0; st < 9; st++) {
                if (lo < hi) {
                    int mid = (lo + hi) >> 1;
                    if (tile[mid] < mykey) lo = mid + 1; else hi = mid;
                }
            }
            atomicAdd(&sRank[ki], lo);
        }
        __syncthreads();
        if (t < 32) {
            int i = blk * 32 + t;
            int rank = sRank[t];
            g_perm[rank] = i;
            g_sorted[rank] = g_sdst[i];
            g_qP[rank] = g_qs[i];
            g_QP[rank] = g_Qs[i];
        }
    }
    gbar(2);

    // ============ Phase 3a: fp32 chunk totals (8 chunks/block, CSZ=4) ========
    {
        int f = t & 63;
        int chunk = blk * 8 + (t >> 6);
        int kbase = chunk * CSZ;
        float sq = 0.f, sQ = 0.f, ssq = 0.f, ssQ = 0.f;
#pragma unroll
        for (int kk = 0; kk < CSZ; kk++) {
            int j = g_perm[kbase + kk];
            float q = g_qP[kbase + kk], Q = g_QP[kbase + kk];  // direct by rank
            float l = g_ltg[(size_t)j * F + f];
            sq += q * l;
            sQ += Q * l;
            ssq += q; ssQ += Q;
        }
        g_ctqT[f][chunk] = sq;
        g_ctQT[f][chunk] = sQ;
        if (f == 0) { g_ctqT[64][chunk] = ssq; g_ctQT[64][chunk] = ssQ; }
    }

    // ============ Phase 3b: output-search precompute (needs only post-gbar(2))
    // Results parked in shared across gbar(3)/gbar(4).
    float* sp = reinterpret_cast<float*>(s_buf);               // 256 splitters
    float* sPart = reinterpret_cast<float*>(s_buf + 1024);     // [32 rows][6][32]
    int* sChunk = reinterpret_cast<int*>(s_buf + 1024 + 24576);
    {
        __syncthreads();   // s_buf handoff (P2 staging done)
        if (t < 256) sp[t] = g_sorted[t * 32 + 31];
        __syncthreads();

        int w = t >> 5;
        int row0 = blk * 32 + w * 2;
        int row1 = row0 + 1;
        float tg0 = -g_ssrc[row0];
        float tg1 = -g_ssrc[row1];

        int lo0 = 0, hi0 = 256, lo1 = 0, hi1 = 256;
#pragma unroll
        for (int st = 0; st < 9; st++) {
            if (lo0 < hi0) { int m = (lo0 + hi0) >> 1; if (sp[m] < tg0) lo0 = m + 1; else hi0 = m; }
            if (lo1 < hi1) { int m = (lo1 + hi1) >> 1; if (sp[m] < tg1) lo1 = m + 1; else hi1 = m; }
        }
        float v0 = g_sorted[lo0 * 32 + lane];
        float v1 = g_sorted[lo1 * 32 + lane];
        unsigned int m0 = __ballot_sync(0xffffffffu, v0 < tg0);
        unsigned int m1 = __ballot_sync(0xffffffffu, v1 < tg1);
        int c0 = lo0 * 32 + __popc(m0);
        int c1 = lo1 * 32 + __popc(m1);

        int ch0 = c0 >> 2, rm0 = c0 & 3, kb0 = ch0 * CSZ;
        int ch1 = c1 >> 2, rm1 = c1 & 3, kb1 = ch1 * CSZ;

        float a_pre0 = 0.f, a_pre1 = 0.f, a_sf0 = 0.f, a_sf1 = 0.f, a_psq = 0.f, a_psQ = 0.f;
        float b_pre0 = 0.f, b_pre1 = 0.f, b_sf0 = 0.f, b_sf1 = 0.f, b_psq = 0.f, b_psQ = 0.f;
#pragma unroll
        for (int kk = 0; kk < CSZ - 1; kk++) {   // max rem = 3
            if (kk < rm0) {
                int j = g_perm[kb0 + kk];
                float q = g_qP[kb0 + kk], Q = g_QP[kb0 + kk];
                float l0 = g_ltg[(size_t)j * F + lane];
                float l1 = g_ltg[(size_t)j * F + 32 + lane];
                a_pre0 += q * l0; a_pre1 += q * l1;
                a_sf0  += Q * l0; a_sf1  += Q * l1;
                a_psq += q; a_psQ += Q;
            }
            if (kk < rm1) {
                int j = g_perm[kb1 + kk];
                float q = g_qP[kb1 + kk], Q = g_QP[kb1 + kk];
                float l0 = g_ltg[(size_t)j * F + lane];
                float l1 = g_ltg[(size_t)j * F + 32 + lane];
                b_pre0 += q * l0; b_pre1 += q * l1;
                b_sf0  += Q * l0; b_sf1  += Q * l1;
                b_psq += q; b_psQ += Q;
            }
        }

        if (lane == 0) { sChunk[w * 2] = ch0; sChunk[w * 2 + 1] = ch1; }
        float* pr0 = sPart + (w * 2) * 192;
        float* pr1 = sPart + (w * 2 + 1) * 192;
        pr0[lane] = a_pre0;       pr0[32 + lane] = a_pre1;
        pr0[64 + lane] = a_sf0;   pr0[96 + lane] = a_sf1;
        pr0[128 + lane] = a_psq;  pr0[160 + lane] = a_psQ;
        pr1[lane] = b_pre0;       pr1[32 + lane] = b_pre1;
        pr1[64 + lane] = b_sf0;   pr1[96 + lane] = b_sf1;
        pr1[128 + lane] = b_psq;  pr1[160 + lane] = b_psQ;
    }
    gbar(3);

    // ============ Phase 4: scan 2048 chunk totals per column (blk<=64) =======
    if (blk <= 64) {
        int f = blk;
        float4 vq = *reinterpret_cast<const float4*>(&g_ctqT[f][4 * t]);
        float4 vQ = *reinterpret_cast<const float4*>(&g_ctQT[f][4 * t]);
        float aq = vq.x + vq.y + vq.z + vq.w;
        float aQ = vQ.x + vQ.y + vQ.z + vQ.w;

        int wp = t >> 5;
        float x = aq, y = aQ;
#pragma unroll
        for (int o = 1; o < 32; o <<= 1) {
            float nx = __shfl_up_sync(0xffffffffu, x, o);
            float ny = __shfl_up_sync(0xffffffffu, y, o);
            if (lane >= o) { x += nx; y += ny; }
        }
        if (lane == 31) { ssx[wp] = x; ssy[wp] = y; }
        __syncthreads();
        if (t < 16) {
            float wx = ssx[t], wy = ssy[t];
            float ix = wx, iy = wy;
#pragma unroll
            for (int o = 1; o < 16; o <<= 1) {
                float nx = __shfl_up_sync(0x0000ffffu, ix, o);
                float ny = __shfl_up_sync(0x0000ffffu, iy, o);
                if (t >= o) { ix += nx; iy += ny; }
            }
            ssx[t] = ix - wx;
            ssy[t] = iy - wy;
        }
        __syncthreads();
        float incx = x + ssx[wp];
        float incy = y + ssy[wp];
        float offq = incx - aq, offQ = incy - aQ;

        g_coq[4 * t + 0][f] = offq;
        g_coq[4 * t + 1][f] = offq + vq.x;
        g_coq[4 * t + 2][f] = offq + vq.x + vq.y;
        g_coq[4 * t + 3][f] = offq + vq.x + vq.y + vq.z;
        g_coQ[4 * t + 0][f] = offQ;
        g_coQ[4 * t + 1][f] = offQ + vQ.x;
        g_coQ[4 * t + 2][f] = offQ + vQ.x + vQ.y;
        g_coQ[4 * t + 3][f] = offQ + vQ.x + vQ.y + vQ.z;
        if (t == 511) { g_coq[CHN][f] = incx; g_coQ[CHN][f] = incy; }
    }
    gbar(4);

    // ============ Phase 5: final combine (short: loads + FMA + store) ========
    {
        int w = t >> 5;
        int row0 = blk * 32 + w * 2;
        int row1 = row0 + 1;
        int ch0 = sChunk[w * 2];
        int ch1 = sChunk[w * 2 + 1];
        const float* pr0 = sPart + (w * 2) * 192;
        const float* pr1 = sPart + (w * 2 + 1) * 192;

        float A_coq0 = g_coq[ch0][lane], A_coq1 = g_coq[ch0][32 + lane];
        float A_coQ0 = g_coQ[ch0][lane], A_coQ1 = g_coQ[ch0][32 + lane];
        float B_coq0 = g_coq[ch1][lane], B_coq1 = g_coq[ch1][32 + lane];
        float B_coQ0 = g_coQ[ch1][lane], B_coQ1 = g_coQ[ch1][32 + lane];
        float tQ0 = g_coQ[CHN][lane], tQ1 = g_coQ[CHN][32 + lane];
        float A_cqs = g_coq[ch0][64], A_cQs = g_coQ[ch0][64];
        float B_cqs = g_coq[ch1][64], B_cQs = g_coQ[ch1][64];
        float tQs = g_coQ[CHN][64];

        float P0 = g_P[row0], p0 = g_p[row0];
        float P1 = g_P[row1], p1 = g_p[row1];

        float Z0 = P0 * (tQs - A_cQs - pr0[160 + lane]) + p0 * (A_cqs + pr0[128 + lane]);
        float Z1 = P1 * (tQs - B_cQs - pr1[160 + lane]) + p1 * (B_cqs + pr1[128 + lane]);
        float iZ0 = 1.0f / Z0;
        float iZ1 = 1.0f / Z1;

        out[(size_t)row0 * F + lane]      = (P0 * (tQ0 - A_coQ0 - pr0[64 + lane]) + p0 * (A_coq0 + pr0[lane])) * iZ0;
        out[(size_t)row0 * F + 32 + lane] = (P0 * (tQ1 - A_coQ1 - pr0[96 + lane]) + p0 * (A_coq1 + pr0[32 + lane])) * iZ0;
        out[(size_t)row1 * F + lane]      = (P1 * (tQ0 - B_coQ0 - pr1[64 + lane]) + p1 * (B_coq0 + pr1[lane])) * iZ1;
        out[(size_t)row1 * F + 32 + lane] = (P1 * (tQ1 - B_coQ1 - pr1[96 + lane]) + p1 * (B_coq1 + pr1[32 + lane])) * iZ1;
    }
}

// ---------------- launch ----------------
extern "C" void kernel_launch(void* const* d_in, const int* in_sizes, int n_in,
                              void* d_out, int out_size) {
    const float* graph = (const float*)d_in[0];
    const float* W     = (const float*)d_in[1];
    const float* a     = (const float*)d_in[2];
    float* out = (float*)d_out;

    gat_fused<<<NBLK, NTHR>>>(graph, W, a, out);
}

// round 17
// speedup vs baseline: 1.0514x; 1.0514x over previous
#include <cuda_runtime.h>
#include <cuda_bf16.h>

#define N 8192
#define F 64
#define TILES 32           // sorted key tiles of 256
#define TSZ 256
#define CHN 2048           // scan chunks
#define CSZ 4              // ranks per chunk
#define NBLK 256
#define NTHR 512

typedef unsigned long long u64;

// ---------------- scratch (no allocations allowed) ----------------
__device__ float g_ltg[N * F];
__device__ float g_ssrc[N];
__device__ float g_sdst[N];
__device__ float g_P[N];
__device__ float g_p[N];
__device__ float g_Qs[N];
__device__ float g_qs[N];
__device__ u64   g_key[N];            // (sortable(sdst)<<32)|idx — unique
__device__ u64   g_tkey[TILES][TSZ];  // per-tile sorted keys (flat-contiguous)
__device__ int   g_perm[N];
__device__ float g_qP[N];             // qs permuted by rank
__device__ float g_QP[N];             // Qs permuted by rank
__device__ float g_sorted[N + 32];    // sdst ascending; +32 pad of +inf
__device__ float g_ctqT[65][CHN];     // transposed chunk totals; row 64 = scalar
__device__ float g_ctQT[65][CHN];
__device__ float g_coq[CHN + 1][72];  // exclusive chunk offsets; row CHN = totals
__device__ float g_coQ[CHN + 1][72];
// sync state — ALL monotonic => CUDA-graph replay safe (no resets needed)
__device__ unsigned int g_epoch;          // per-launch ticket: epoch = ticket/NBLK
__device__ unsigned int g_keyflag[TILES]; // +8 per tile per launch
__device__ unsigned int g_sortflag;       // +32 per launch
__device__ unsigned int g_barc[8];        // full-barrier counters

__device__ __forceinline__ unsigned int f2sort(float f) {
    unsigned int u = __float_as_uint(f);
    return (u & 0x80000000u) ? ~u : (u | 0x80000000u);
}

// Full grid barrier (measured-best simple variant).
__device__ __forceinline__ void gbar(int id) {
    __syncthreads();
    if (threadIdx.x == 0) {
        __threadfence();
        unsigned int old = atomicAdd(&g_barc[id], 1u);
        unsigned int target = (old / NBLK + 1u) * NBLK;
        volatile unsigned int* p = &g_barc[id];
        while (*p < target) { __nanosleep(64); }
        __threadfence();
    }
    __syncthreads();
}

__global__ __launch_bounds__(NTHR, 2)
void gat_fused(const float* __restrict__ graph,
               const float* __restrict__ W,
               const float* __restrict__ a,
               float* __restrict__ out) {
    // 32KB shared reuse: sW [0,16K) + sort tile [16K,18K) (P0/P1) /
    //                    rank stage full 32KB (P2) / splitters (P5)
    __shared__ __align__(16) unsigned char s_buf[32768];
    __shared__ float sa[2 * F];
    __shared__ float swv[2 * F];       // wv1 | wv2
    __shared__ int   sRank[32];
    __shared__ float ssx[16], ssy[16];
    __shared__ unsigned int sEpoch;

    int t = threadIdx.x;
    int blk = blockIdx.x;
    int lane = t & 31;

    float* sW = reinterpret_cast<float*>(s_buf);

    if (t == 0) sEpoch = atomicAdd(&g_epoch, 1u) / NBLK;

    // ============ Phase 0: W->smem, wv = W·a halves, scalars/exps/keys =======
    {
        for (int i = t; i < F * F; i += NTHR) sW[i] = W[i];
        if (t < 2 * F) sa[t] = a[t];
        if (blk == 0 && t < 32) g_sorted[N + t] = __int_as_float(0x7f800000);
        __syncthreads();

        if (t < F) {
            float s1 = 0.f, s2 = 0.f;
            const float4* wr = reinterpret_cast<const float4*>(&sW[t * F]);
            const float4* a1 = reinterpret_cast<const float4*>(&sa[0]);
            const float4* a2 = reinterpret_cast<const float4*>(&sa[F]);
#pragma unroll
            for (int f4 = 0; f4 < F / 4; f4++) {
                float4 w = wr[f4], v1 = a1[f4], v2 = a2[f4];
                s1 += w.x * v1.x + w.y * v1.y + w.z * v1.z + w.w * v1.w;
                s2 += w.x * v2.x + w.y * v2.y + w.z * v2.z + w.w * v2.w;
            }
            swv[t] = s1;
            swv[F + t] = s2;
        }
        __syncthreads();

        int row = blk * 32 + (t >> 4);
        int q = t & 15;
        float4 g = __ldg(&reinterpret_cast<const float4*>(graph)[(size_t)row * 16 + q]);
        float4 w1 = reinterpret_cast<const float4*>(swv)[q];
        float4 w2 = reinterpret_cast<const float4*>(swv)[16 + q];
        float s1 = g.x * w1.x + g.y * w1.y + g.z * w1.z + g.w * w1.w;
        float s2 = g.x * w2.x + g.y * w2.y + g.z * w2.z + g.w * w2.w;
        s1 += __shfl_xor_sync(0xffffffffu, s1, 1);
        s1 += __shfl_xor_sync(0xffffffffu, s1, 2);
        s1 += __shfl_xor_sync(0xffffffffu, s1, 4);
        s1 += __shfl_xor_sync(0xffffffffu, s1, 8);
        s2 += __shfl_xor_sync(0xffffffffu, s2, 1);
        s2 += __shfl_xor_sync(0xffffffffu, s2, 2);
        s2 += __shfl_xor_sync(0xffffffffu, s2, 4);
        s2 += __shfl_xor_sync(0xffffffffu, s2, 8);
        if (q == 0) {
            g_ssrc[row] = s1;
            g_sdst[row] = s2;
            g_P[row]  = expf(s1);
            g_p[row]  = expf(0.2f * s1);
            g_Qs[row] = expf(s2);
            g_qs[row] = expf(0.2f * s2);
            g_key[row] = ((u64)f2sort(s2) << 32) | (unsigned int)row;
        }
        __syncthreads();
        if (t == 0) {   // publish this block's 32 keys to its covering tile
            __threadfence();
            atomicAdd(&g_keyflag[blk >> 3], 1u);
        }
    }

    // ============ Phase 1a (blk<32): wait for 8 key-producers, count-sort ====
    if (blk < TILES) {
        if (t == 0) {
            volatile unsigned int* kf = &g_keyflag[blk];
            unsigned int tgt = 8u * (sEpoch + 1u);
            while (*kf < tgt) { __nanosleep(32); }
        }
        __syncthreads();
        u64* sk = reinterpret_cast<u64*>(s_buf + 16384);  // 2KB, above sW
        if (t < 256) sk[t] = g_key[blk * 256 + t];
        __syncthreads();
        if (t < 256) {
            u64 mykey = sk[t];
            int cnt = 0;
#pragma unroll 8
            for (int i = 0; i < 256; i++) cnt += (int)(sk[i] < mykey);
            g_tkey[blk][cnt] = mykey;
        }
        __syncthreads();
        if (t == 0) {
            __threadfence();
            atomicAdd(&g_sortflag, 1u);
        }
    }

    // ============ Phase 1b (all blocks): GEMM — independent, starts early ====
    {
        int rp = t >> 5;
        int fs2 = (t & 31) * 2;
        int r0 = blk * 32 + rp * 2;
        int r1 = r0 + 1;

        float a00 = 0.f, a01 = 0.f, a10 = 0.f, a11 = 0.f;
        const float4* g4 = reinterpret_cast<const float4*>(graph);
#pragma unroll
        for (int k4i = 0; k4i < F / 4; k4i++) {
            float4 g0 = __ldg(&g4[(size_t)r0 * 16 + k4i]);
            float4 g1 = __ldg(&g4[(size_t)r1 * 16 + k4i]);
            float gv0[4] = {g0.x, g0.y, g0.z, g0.w};
            float gv1[4] = {g1.x, g1.y, g1.z, g1.w};
#pragma unroll
            for (int kk = 0; kk < 4; kk++) {
                float2 w = *reinterpret_cast<const float2*>(&sW[(k4i * 4 + kk) * F + fs2]);
                a00 += gv0[kk] * w.x;
                a01 += gv0[kk] * w.y;
                a10 += gv1[kk] * w.x;
                a11 += gv1[kk] * w.y;
            }
        }
        *reinterpret_cast<float2*>(&g_ltg[(size_t)r0 * F + fs2]) = make_float2(a00, a01);
        *reinterpret_cast<float2*>(&g_ltg[(size_t)r1 * F + fs2]) = make_float2(a10, a11);
    }

    // ============ Phase 2: wait all tiles sorted, rank own 32 keys ===========
    {
        if (t == 0) {
            volatile unsigned int* sf = &g_sortflag;
            unsigned int tgt = 32u * (sEpoch + 1u);
            while (*sf < tgt) { __nanosleep(32); }
        }
        __syncthreads();

        u64* tb = reinterpret_cast<u64*>(s_buf);  // 4096 u64 = 32KB (sW done)
        const u64* tkf = &g_tkey[0][0];
        int ki = t & 31;
        int tloc = t >> 5;
        u64 mykey = g_key[blk * 32 + ki];
        if (t < 32) sRank[t] = 0;

#pragma unroll 1
        for (int round = 0; round < 2; round++) {
            __syncthreads();
#pragma unroll
            for (int r = 0; r < 8; r++)
                tb[r * 512 + t] = tkf[round * 4096 + r * 512 + t];
            __syncthreads();

            const u64* tile = tb + tloc * 256;
            int lo = 0, hi = 256;
#pragma unroll
            for (int st = 0; st < 9; st++) {
                if (lo < hi) {
                    int mid = (lo + hi) >> 1;
                    if (tile[mid] < mykey) lo = mid + 1; else hi = mid;
                }
            }
            atomicAdd(&sRank[ki], lo);
        }
        __syncthreads();
        if (t < 32) {
            int i = blk * 32 + t;
            int rank = sRank[t];
            g_perm[rank] = i;
            g_sorted[rank] = g_sdst[i];
            g_qP[rank] = g_qs[i];
            g_QP[rank] = g_Qs[i];
        }
    }
    gbar(0);

    // ============ Phase 3: fp32 chunk totals (8 chunks/block, CSZ=4) =========
    {
        int f = t & 63;
        int chunk = blk * 8 + (t >> 6);
        int kbase = chunk * CSZ;
        float sq = 0.f, sQ = 0.f, ssq = 0.f, ssQ = 0.f;
#pragma unroll
        for (int kk = 0; kk < CSZ; kk++) {
            int j = g_perm[kbase + kk];
            float q = g_qP[kbase + kk], Q = g_QP[kbase + kk];
            float l = g_ltg[(size_t)j * F + f];
            sq += q * l;
            sQ += Q * l;
            ssq += q; ssQ += Q;
        }
        g_ctqT[f][chunk] = sq;
        g_ctQT[f][chunk] = sQ;
        if (f == 0) { g_ctqT[64][chunk] = ssq; g_ctQT[64][chunk] = ssQ; }
    }
    gbar(1);

    // ============ Phase 4: scan 2048 chunk totals per column (blk<=64) =======
    if (blk <= 64) {
        int f = blk;
        float4 vq = *reinterpret_cast<const float4*>(&g_ctqT[f][4 * t]);
        float4 vQ = *reinterpret_cast<const float4*>(&g_ctQT[f][4 * t]);
        float aq = vq.x + vq.y + vq.z + vq.w;
        float aQ = vQ.x + vQ.y + vQ.z + vQ.w;

        int wp = t >> 5;
        float x = aq, y = aQ;
#pragma unroll
        for (int o = 1; o < 32; o <<= 1) {
            float nx = __shfl_up_sync(0xffffffffu, x, o);
            float ny = __shfl_up_sync(0xffffffffu, y, o);
            if (lane >= o) { x += nx; y += ny; }
        }
        if (lane == 31) { ssx[wp] = x; ssy[wp] = y; }
        __syncthreads();
        if (t < 16) {
            float wx = ssx[t], wy = ssy[t];
            float ix = wx, iy = wy;
#pragma unroll
            for (int o = 1; o < 16; o <<= 1) {
                float nx = __shfl_up_sync(0x0000ffffu, ix, o);
                float ny = __shfl_up_sync(0x0000ffffu, iy, o);
                if (t >= o) { ix += nx; iy += ny; }
            }
            ssx[t] = ix - wx;
            ssy[t] = iy - wy;
        }
        __syncthreads();
        float incx = x + ssx[wp];
        float incy = y + ssy[wp];
        float offq = incx - aq, offQ = incy - aQ;

        g_coq[4 * t + 0][f] = offq;
        g_coq[4 * t + 1][f] = offq + vq.x;
        g_coq[4 * t + 2][f] = offq + vq.x + vq.y;
        g_coq[4 * t + 3][f] = offq + vq.x + vq.y + vq.z;
        g_coQ[4 * t + 0][f] = offQ;
        g_coQ[4 * t + 1][f] = offQ + vQ.x;
        g_coQ[4 * t + 2][f] = offQ + vQ.x + vQ.y;
        g_coQ[4 * t + 3][f] = offQ + vQ.x + vQ.y + vQ.z;
        if (t == 511) { g_coq[CHN][f] = incx; g_coQ[CHN][f] = incy; }
    }
    gbar(2);

    // ============ Phase 5: output — search + tail gather + combine ===========
    {
        float* sp = reinterpret_cast<float*>(s_buf);  // 256 splitters
        if (t < 256) sp[t] = g_sorted[t * 32 + 31];
        __syncthreads();

        int w = t >> 5;
        int row0 = blk * 32 + w * 2;
        int row1 = row0 + 1;
        float tg0 = -g_ssrc[row0];
        float tg1 = -g_ssrc[row1];

        int lo0 = 0, hi0 = 256, lo1 = 0, hi1 = 256;
#pragma unroll
        for (int st = 0; st < 9; st++) {
            if (lo0 < hi0) { int m = (lo0 + hi0) >> 1; if (sp[m] < tg0) lo0 = m + 1; else hi0 = m; }
            if (lo1 < hi1) { int m = (lo1 + hi1) >> 1; if (sp[m] < tg1) lo1 = m + 1; else hi1 = m; }
        }
        float v0 = g_sorted[lo0 * 32 + lane];
        float v1 = g_sorted[lo1 * 32 + lane];
        unsigned int m0 = __ballot_sync(0xffffffffu, v0 < tg0);
        unsigned int m1 = __ballot_sync(0xffffffffu, v1 < tg1);
        int c0 = lo0 * 32 + __popc(m0);
        int c1 = lo1 * 32 + __popc(m1);

        int ch0 = c0 >> 2, rm0 = c0 & 3, kb0 = ch0 * CSZ;
        int ch1 = c1 >> 2, rm1 = c1 & 3, kb1 = ch1 * CSZ;

        float a_pre0 = 0.f, a_pre1 = 0.f, a_sf0 = 0.f, a_sf1 = 0.f, a_psq = 0.f, a_psQ = 0.f;
        float b_pre0 = 0.f, b_pre1 = 0.f, b_sf0 = 0.f, b_sf1 = 0.f, b_psq = 0.f, b_psQ = 0.f;
#pragma unroll
        for (int kk = 0; kk < CSZ - 1; kk++) {   // max rem = 3
            if (kk < rm0) {
                int j = g_perm[kb0 + kk];
                float q = g_qP[kb0 + kk], Q = g_QP[kb0 + kk];
                float l0 = g_ltg[(size_t)j * F + lane];
                float l1 = g_ltg[(size_t)j * F + 32 + lane];
                a_pre0 += q * l0; a_pre1 += q * l1;
                a_sf0  += Q * l0; a_sf1  += Q * l1;
                a_psq += q; a_psQ += Q;
            }
            if (kk < rm1) {
                int j = g_perm[kb1 + kk];
                float q = g_qP[kb1 + kk], Q = g_QP[kb1 + kk];
                float l0 = g_ltg[(size_t)j * F + lane];
                float l1 = g_ltg[(size_t)j * F + 32 + lane];
                b_pre0 += q * l0; b_pre1 += q * l1;
                b_sf0  += Q * l0; b_sf1  += Q * l1;
                b_psq += q; b_psQ += Q;
            }
        }

        float A_coq0 = g_coq[ch0][lane], A_coq1 = g_coq[ch0][32 + lane];
        float A_coQ0 = g_coQ[ch0][lane], A_coQ1 = g_coQ[ch0][32 + lane];
        float B_coq0 = g_coq[ch1][lane], B_coq1 = g_coq[ch1][32 + lane];
        float B_coQ0 = g_coQ[ch1][lane], B_coQ1 = g_coQ[ch1][32 + lane];
        float tQ0 = g_coQ[CHN][lane], tQ1 = g_coQ[CHN][32 + lane];
        float A_cqs = g_coq[ch0][64], A_cQs = g_coQ[ch0][64];
        float B_cqs = g_coq[ch1][64], B_cQs = g_coQ[ch1][64];
        float tQs = g_coQ[CHN][64];

        float P0 = g_P[row0], p0 = g_p[row0];
        float P1 = g_P[row1], p1 = g_p[row1];
        float Z0 = P0 * (tQs - A_cQs - a_psQ) + p0 * (A_cqs + a_psq);
        float Z1 = P1 * (tQs - B_cQs - b_psQ) + p1 * (B_cqs + b_psq);
        float iZ0 = 1.0f / Z0;
        float iZ1 = 1.0f / Z1;

        out[(size_t)row0 * F + lane]      = (P0 * (tQ0 - A_coQ0 - a_sf0) + p0 * (A_coq0 + a_pre0)) * iZ0;
        out[(size_t)row0 * F + 32 + lane] = (P0 * (tQ1 - A_coQ1 - a_sf1) + p0 * (A_coq1 + a_pre1)) * iZ0;
        out[(size_t)row1 * F + lane]      = (P1 * (tQ0 - B_coQ0 - b_sf0) + p1 * (B_coq0 + b_pre0)) * iZ1;
        out[(size_t)row1 * F + 32 + lane] = (P1 * (tQ1 - B_coQ1 - b_sf1) + p1 * (B_coq1 + b_pre1)) * iZ1;
    }
}

// ---------------- launch ----------------
extern "C" void kernel_launch(void* const* d_in, const int* in_sizes, int n_in,
                              void* d_out, int out_size) {
    const float* graph = (const float*)d_in[0];
    const float* W     = (const float*)d_in[1];
    const float* a     = (const float*)d_in[2];
    float* out = (float*)d_out;

    gat_fused<<<NBLK, NTHR>>>(graph, W, a, out);
}